// round 8
// baseline (speedup 1.0000x reference)
#include <cuda_runtime.h>
#include <cstdint>
#include <math.h>

#define NN 1024
#define KK 512
#define TILE 64            // CTA tile (square, triangular-symmetric)
#define KC 64              // k-chunk
#define NCH (KK / KC)      // 8
#define MARGIN 1.0f

#define PITCH 68           // floats per smem row (pad 4 -> conflict-free frags)
#define PITCHB (PITCH * 4) // 272 B
#define MATB (TILE * PITCHB)   // 17408 per matrix
#define BUFB (2 * MATB)        // 34816 per stage (A+B)
#define NSTAGE 3
#define DYNB (NSTAGE * BUFB)   // 104448

// Scratch (device globals — allocation forbidden)
__device__ float g_dist[NN * NN];
__device__ float g_losses[NN];
__device__ int   g_clsidx[32 * 128];
__device__ int   g_clscnt[32];
__device__ unsigned int g_count;   // zero-init; self-resets each launch

// ---------------------------------------------------------------------------
static __device__ __forceinline__ uint32_t sptr(const void* p) {
    uint32_t a;
    asm("{ .reg .u64 t; cvta.to.shared.u64 t, %1; cvt.u32.u64 %0, t; }"
        : "=r"(a) : "l"(p));
    return a;
}
static __device__ __forceinline__ void cp16(uint32_t dst, const void* src) {
    asm volatile("cp.async.cg.shared.global [%0], [%1], 16;" :: "r"(dst), "l"(src));
}
#define CP_COMMIT() asm volatile("cp.async.commit_group;" ::: "memory")

static __device__ __forceinline__ void mma_tf32(
    float& d0, float& d1, float& d2, float& d3,
    float a0, float a1, float a2, float a3, float b0, float b1)
{
    asm volatile(
        "mma.sync.aligned.m16n8k8.row.col.f32.tf32.tf32.f32 "
        "{%0,%1,%2,%3}, {%4,%5,%6,%7}, {%8,%9}, {%0,%1,%2,%3};"
        : "+f"(d0), "+f"(d1), "+f"(d2), "+f"(d3)
        : "r"(__float_as_uint(a0)), "r"(__float_as_uint(a1)),
          "r"(__float_as_uint(a2)), "r"(__float_as_uint(a3)),
          "r"(__float_as_uint(b0)), "r"(__float_as_uint(b1)));
}

// ---------------------------------------------------------------------------
// Kernel 1: tf32 mma.sync symmetric distance GEMM, fused norms + sqrt,
// 3-stage cp.async pipeline (one barrier per chunk). CTAs 0..31 additionally
// build the per-class member lists (overlapped with the first cp.async wait).
// ---------------------------------------------------------------------------
__global__ __launch_bounds__(256) void dist_mma_kernel(
    const float* __restrict__ X, const int* __restrict__ labels,
    float* __restrict__ D)
{
    extern __shared__ __align__(16) char dyn[];
    __shared__ float sqA_s[TILE], sqB_s[TILE];

    const int tid  = threadIdx.x;
    const int wid  = tid >> 5;
    const int lane = tid & 31;
    const int g    = lane >> 2;
    const int tg   = lane & 3;

    // triangular block decode
    const int nb = NN / TILE;          // 16
    int rem = blockIdx.x, bi = 0;
    while (rem >= nb - bi) { rem -= nb - bi; bi++; }
    const int bj = bi + rem;
    const int bm = bi * TILE;
    const int bn = bj * TILE;

    const int wm = (wid >> 2) * 32;
    const int wn = (wid & 3) * 16;

    const uint32_t smem = sptr(dyn);

    auto issue = [&](int c, int buf) {
        const uint32_t sb = smem + buf * BUFB;
        const float* XA = X + (size_t)bm * KK + c * KC;
        const float* XB = X + (size_t)bn * KK + c * KC;
#pragma unroll
        for (int it = 0; it < 4; it++) {
            int idx = tid + it * 256;
            int row = idx >> 4;
            int kq  = idx & 15;
            uint32_t doff = row * PITCHB + kq * 16;
            cp16(sb + doff,        XA + (size_t)row * KK + kq * 4);
            cp16(sb + MATB + doff, XB + (size_t)row * KK + kq * 4);
        }
        CP_COMMIT();
    };

    issue(0, 0);
    issue(1, 1);

    // class-list build (overlaps the first wait): CTA c < 32, warp 0 only
    if (blockIdx.x < 32 && wid == 0) {
        const int w = blockIdx.x;
        int base = 0;
        for (int j0 = 0; j0 < NN; j0 += 32) {
            int j = j0 + lane;
            int m = (__ldg(&labels[j]) == w);
            unsigned bal = __ballot_sync(0xffffffffu, m);
            if (m) {
                int p = base + __popc(bal & ((1u << lane) - 1u));
                if (p < 128) g_clsidx[w * 128 + p] = j;
            }
            base += __popc(bal);
        }
        if (lane == 0) g_clscnt[w] = base < 128 ? base : 128;
    }

    float acc[2][2][4];
#pragma unroll
    for (int mt = 0; mt < 2; mt++)
#pragma unroll
        for (int nt = 0; nt < 2; nt++)
#pragma unroll
            for (int e = 0; e < 4; e++) acc[mt][nt][e] = 0.0f;

    float sa[2][2] = {};
    float sbn[2]   = {};
    const bool awarp = ((wid & 3) == 0);
    const bool bwarp = ((wid >> 2) == 0);

    for (int c = 0; c < NCH; c++) {
        if (c < NCH - 1) asm volatile("cp.async.wait_group 1;" ::: "memory");
        else             asm volatile("cp.async.wait_group 0;" ::: "memory");
        __syncthreads();                 // single barrier per chunk

        const float* As = (const float*)(dyn + (c % NSTAGE) * BUFB);
        const float* Bs = (const float*)(dyn + (c % NSTAGE) * BUFB + MATB);

#pragma unroll
        for (int s = 0; s < KC / 8; s++) {
            float a[2][4];
#pragma unroll
            for (int mt = 0; mt < 2; mt++) {
                const float* p = As + (wm + mt * 16 + g) * PITCH + s * 8 + tg;
                a[mt][0] = p[0];
                a[mt][2] = p[4];
                a[mt][1] = p[8 * PITCH];
                a[mt][3] = p[8 * PITCH + 4];
            }
            float b[2][2];
#pragma unroll
            for (int nt = 0; nt < 2; nt++) {
                const float* p = Bs + (wn + nt * 8 + g) * PITCH + s * 8 + tg;
                b[nt][0] = p[0];
                b[nt][1] = p[4];
            }
            if (awarp) {
#pragma unroll
                for (int mt = 0; mt < 2; mt++) {
                    sa[mt][0] += a[mt][0] * a[mt][0] + a[mt][2] * a[mt][2];
                    sa[mt][1] += a[mt][1] * a[mt][1] + a[mt][3] * a[mt][3];
                }
            }
            if (bwarp) {
#pragma unroll
                for (int nt = 0; nt < 2; nt++)
                    sbn[nt] += b[nt][0] * b[nt][0] + b[nt][1] * b[nt][1];
            }
#pragma unroll
            for (int mt = 0; mt < 2; mt++)
#pragma unroll
                for (int nt = 0; nt < 2; nt++)
                    mma_tf32(acc[mt][nt][0], acc[mt][nt][1], acc[mt][nt][2], acc[mt][nt][3],
                             a[mt][0], a[mt][1], a[mt][2], a[mt][3],
                             b[nt][0], b[nt][1]);
        }
        if (c + 2 < NCH) issue(c + 2, (c + 2) % NSTAGE);   // distinct stage: no barrier
    }

    // fused-norm reduce
    if (awarp) {
#pragma unroll
        for (int mt = 0; mt < 2; mt++)
#pragma unroll
            for (int h = 0; h < 2; h++) {
                float v = sa[mt][h];
                v += __shfl_xor_sync(0xffffffffu, v, 1);
                v += __shfl_xor_sync(0xffffffffu, v, 2);
                if (tg == 0) sqA_s[wm + mt * 16 + h * 8 + g] = v;
            }
    }
    if (bwarp) {
#pragma unroll
        for (int nt = 0; nt < 2; nt++) {
            float v = sbn[nt];
            v += __shfl_xor_sync(0xffffffffu, v, 1);
            v += __shfl_xor_sync(0xffffffffu, v, 2);
            if (tg == 0) sqB_s[wn + nt * 8 + g] = v;
        }
    }
    __syncthreads();

    // epilogue: d = sqrt(relu(sqA + sqB - 2 dot)); store + mirror
    const bool offdiag = (bi != bj);
#pragma unroll
    for (int mt = 0; mt < 2; mt++) {
        const int r0 = wm + mt * 16 + g;
        const float sq0 = sqA_s[r0];
        const float sq1 = sqA_s[r0 + 8];
        const int gi0 = bm + r0, gi1 = gi0 + 8;
#pragma unroll
        for (int nt = 0; nt < 2; nt++) {
            const int cc = wn + nt * 8 + 2 * tg;
            const float sb0 = sqB_s[cc], sb1 = sqB_s[cc + 1];
            const int gj0 = bn + cc, gj1 = gj0 + 1;
            float2 o0, o1;
            o0.x = sqrtf(fmaxf(sq0 + sb0 - 2.0f * acc[mt][nt][0], 0.0f));
            o0.y = sqrtf(fmaxf(sq0 + sb1 - 2.0f * acc[mt][nt][1], 0.0f));
            o1.x = sqrtf(fmaxf(sq1 + sb0 - 2.0f * acc[mt][nt][2], 0.0f));
            o1.y = sqrtf(fmaxf(sq1 + sb1 - 2.0f * acc[mt][nt][3], 0.0f));
            *(float2*)(D + (size_t)gi0 * NN + gj0) = o0;
            *(float2*)(D + (size_t)gi1 * NN + gj0) = o1;
            if (offdiag) {
                D[(size_t)gj0 * NN + gi0] = o0.x;
                D[(size_t)gj1 * NN + gi0] = o0.y;
                D[(size_t)gj0 * NN + gi1] = o1.x;
                D[(size_t)gj1 * NN + gi1] = o1.y;
            }
        }
    }
}

// ---------------------------------------------------------------------------
// Kernel 2: per-anchor loss, label-free main loop.
//   loss_i = sum_{all j} f(d_ij) - sum_{j in pos(i)} f(d_ij)
//   f(t' = t - m) = SS[idx] - (npos - idx) * t',  idx = #{p : dp <= t'}
// Positives gathered via precomputed class lists. Fused final reduce.
// ---------------------------------------------------------------------------
__global__ __launch_bounds__(256) void anchor_loss_kernel(
    const float* __restrict__ D, const int* __restrict__ labels, int N,
    float* __restrict__ out)
{
    __shared__ float posv[128];
    __shared__ float sorted[128];
    __shared__ float ss[129];
    __shared__ float red[8];
    __shared__ int   sh_islast;

    const int i = blockIdx.x;
    const int tid = threadIdx.x;
    const int lane = tid & 31;
    const int wid = tid >> 5;
    const int li = __ldg(&labels[i]);
    const float* row = D + (size_t)i * N;
    const int npos = g_clscnt[li];

    if (tid < 128) sorted[tid] = 3.0e30f;                 // INF pad
    if (tid < npos) posv[tid] = __ldg(&row[g_clsidx[li * 128 + tid]]);
    __syncthreads();

    // stable rank sort (npos <= 128)
    if (tid < npos) {
        float v = posv[tid];
        int rank = 0;
        for (int j = 0; j < npos; j++) {
            float w = posv[j];
            rank += (w < v) || (w == v && j < tid);
        }
        sorted[rank] = v;
    }
    __syncthreads();

    // warp 0: suffix sums over 128 slots
    if (tid < 32) {
        float v0 = (4 * tid + 0 < npos) ? sorted[4 * tid + 0] : 0.f;
        float v1 = (4 * tid + 1 < npos) ? sorted[4 * tid + 1] : 0.f;
        float v2 = (4 * tid + 2 < npos) ? sorted[4 * tid + 2] : 0.f;
        float v3 = (4 * tid + 3 < npos) ? sorted[4 * tid + 3] : 0.f;
        float s3 = v3, s2 = v2 + s3, s1 = v1 + s2, s0 = v0 + s1;
        float x = s0;
#pragma unroll
        for (int d = 1; d < 32; d <<= 1) {
            float y = __shfl_down_sync(0xffffffffu, x, d);
            if (tid + d < 32) x += y;
        }
        float carry = x - s0;
        ss[4 * tid + 0] = s0 + carry;
        ss[4 * tid + 1] = s1 + carry;
        ss[4 * tid + 2] = s2 + carry;
        ss[4 * tid + 3] = s3 + carry;
        if (tid == 0) ss[128] = 0.f;
    }
    __syncthreads();

    const float fnp = (float)npos;
    float sum = 0.0f;
    // main loop over ALL j (no label checks)
#pragma unroll
    for (int q = 0; q < 4; q++) {
        float t = __ldg(&row[tid + q * 256]) - MARGIN;
        int pos = 0;
#pragma unroll
        for (int s = 64; s > 0; s >>= 1)
            if (sorted[pos + s - 1] <= t) pos += s;
        sum += ss[pos] - (fnp - (float)pos) * t;
    }
    // subtract positive-j contributions (same f, float-identical search)
    if (tid < npos) {
        float t = sorted[tid] - MARGIN;
        int pos = 0;
#pragma unroll
        for (int s = 64; s > 0; s >>= 1)
            if (sorted[pos + s - 1] <= t) pos += s;
        sum -= ss[pos] - (fnp - (float)pos) * t;
    }

    // shfl warp reduce -> 8 partials -> thread 0 (deterministic)
#pragma unroll
    for (int o = 16; o; o >>= 1) sum += __shfl_xor_sync(0xffffffffu, sum, o);
    if (lane == 0) red[wid] = sum;
    __syncthreads();
    if (tid == 0) {
        float tot = 0.f;
#pragma unroll
        for (int w = 0; w < 8; w++) tot += red[w];
        g_losses[i] = tot;
        __threadfence();
        unsigned v = atomicAdd(&g_count, 1u);
        sh_islast = (v == (unsigned)(gridDim.x - 1));
    }
    __syncthreads();

    // last-done block: deterministic final reduce
    if (sh_islast) {
        float s = 0.0f;
        for (int j = tid; j < N; j += 256) s += g_losses[j];
#pragma unroll
        for (int o = 16; o; o >>= 1) s += __shfl_xor_sync(0xffffffffu, s, o);
        if (lane == 0) red[wid] = s;
        __syncthreads();
        if (tid == 0) {
            float tot = 0.f;
#pragma unroll
            for (int w = 0; w < 8; w++) tot += red[w];
            out[0] = tot / ((float)N + 1e-8f);
            g_count = 0u;
        }
    }
}

// ---------------------------------------------------------------------------
extern "C" void kernel_launch(void* const* d_in, const int* in_sizes, int n_in,
                              void* d_out, int out_size)
{
    const float* features = (const float*)d_in[0];
    const int*   labels   = (const int*)d_in[1];
    float*       out      = (float*)d_out;

    const int N = in_sizes[1];            // 1024

    float* D;
    cudaGetSymbolAddress((void**)&D, g_dist);

    cudaFuncSetAttribute(dist_mma_kernel,
                         cudaFuncAttributeMaxDynamicSharedMemorySize, DYNB);

    const int nb = NN / TILE;             // 16 -> 136 CTAs
    dist_mma_kernel<<<nb * (nb + 1) / 2, 256, DYNB>>>(features, labels, D);
    anchor_loss_kernel<<<N, 256>>>(D, labels, N, out);
}

// round 9
// speedup vs baseline: 1.1620x; 1.1620x over previous
#include <cuda_runtime.h>
#include <cstdint>
#include <math.h>

#define NN 1024
#define KK 512
#define TILE 64            // CTA tile (square, triangular-symmetric)
#define KC 64              // k-chunk
#define NCH (KK / KC)      // 8
#define MARGIN 1.0f

#define PITCH 68           // floats per smem row (pad 4 -> conflict-free frags)
#define PITCHB (PITCH * 4) // 272 B
#define MATB (TILE * PITCHB)   // 17408 per matrix
#define BUFB (2 * MATB)        // 34816 per buffer (A+B)
#define DYNB (2 * BUFB)        // 69632 double-buffered

// Scratch (device globals — allocation forbidden)
__device__ float g_dist[NN * NN];
__device__ float g_losses[NN];
__device__ int   g_clsidx[32 * 128];
__device__ int   g_clscnt[32];
__device__ unsigned int g_count;   // zero-init; self-resets each launch

// ---------------------------------------------------------------------------
static __device__ __forceinline__ uint32_t sptr(const void* p) {
    uint32_t a;
    asm("{ .reg .u64 t; cvta.to.shared.u64 t, %1; cvt.u32.u64 %0, t; }"
        : "=r"(a) : "l"(p));
    return a;
}
static __device__ __forceinline__ void cp16(uint32_t dst, const void* src) {
    asm volatile("cp.async.cg.shared.global [%0], [%1], 16;" :: "r"(dst), "l"(src));
}
#define CP_COMMIT() asm volatile("cp.async.commit_group;" ::: "memory")

static __device__ __forceinline__ void mma_tf32(
    float& d0, float& d1, float& d2, float& d3,
    float a0, float a1, float a2, float a3, float b0, float b1)
{
    asm volatile(
        "mma.sync.aligned.m16n8k8.row.col.f32.tf32.tf32.f32 "
        "{%0,%1,%2,%3}, {%4,%5,%6,%7}, {%8,%9}, {%0,%1,%2,%3};"
        : "+f"(d0), "+f"(d1), "+f"(d2), "+f"(d3)
        : "r"(__float_as_uint(a0)), "r"(__float_as_uint(a1)),
          "r"(__float_as_uint(a2)), "r"(__float_as_uint(a3)),
          "r"(__float_as_uint(b0)), "r"(__float_as_uint(b1)));
}

// ---------------------------------------------------------------------------
// Kernel 1: tf32 mma.sync symmetric distance GEMM, fused norms + sqrt.
// 136 CTAs (triangular 64x64 tiles), 256 thr, 2-stage cp.async (R7-proven).
// CTAs 0..31: build class member lists from smem-staged labels (~1us, hidden).
// ---------------------------------------------------------------------------
__global__ __launch_bounds__(256) void dist_mma_kernel(
    const float* __restrict__ X, const int* __restrict__ labels,
    float* __restrict__ D)
{
    extern __shared__ __align__(16) char dyn[];
    __shared__ float sqA_s[TILE], sqB_s[TILE];
    __shared__ int   lbl_s[NN];        // used only by CTAs < 32

    const int tid  = threadIdx.x;
    const int wid  = tid >> 5;
    const int lane = tid & 31;
    const int g    = lane >> 2;
    const int tg   = lane & 3;

    // triangular block decode
    const int nb = NN / TILE;          // 16
    int rem = blockIdx.x, bi = 0;
    while (rem >= nb - bi) { rem -= nb - bi; bi++; }
    const int bj = bi + rem;
    const int bm = bi * TILE;
    const int bn = bj * TILE;

    const int wm = (wid >> 2) * 32;
    const int wn = (wid & 3) * 16;

    const uint32_t smem = sptr(dyn);

    auto issue = [&](int c, int buf) {
        const uint32_t sb = smem + buf * BUFB;
        const float* XA = X + (size_t)bm * KK + c * KC;
        const float* XB = X + (size_t)bn * KK + c * KC;
#pragma unroll
        for (int it = 0; it < 4; it++) {
            int idx = tid + it * 256;
            int row = idx >> 4;
            int kq  = idx & 15;
            uint32_t doff = row * PITCHB + kq * 16;
            cp16(sb + doff,        XA + (size_t)row * KK + kq * 4);
            cp16(sb + MATB + doff, XB + (size_t)row * KK + kq * 4);
        }
        CP_COMMIT();
    };

    issue(0, 0);
    issue(1, 1);

    // class-list build, hidden behind the first cp.async wait.
    // Stage labels via 4 parallel coalesced LDG rounds, then ballot from smem.
    if (blockIdx.x < 32) {
#pragma unroll
        for (int j = 0; j < 4; j++) lbl_s[tid + j * 256] = __ldg(&labels[tid + j * 256]);
        __syncthreads();
        if (wid == 0) {
            const int w = blockIdx.x;
            int base = 0;
            for (int j0 = 0; j0 < NN; j0 += 32) {
                int m = (lbl_s[j0 + lane] == w);
                unsigned bal = __ballot_sync(0xffffffffu, m);
                if (m) {
                    int p = base + __popc(bal & ((1u << lane) - 1u));
                    if (p < 128) g_clsidx[w * 128 + p] = j0 + lane;
                }
                base += __popc(bal);
            }
            if (lane == 0) g_clscnt[w] = base < 128 ? base : 128;
        }
    }

    float acc[2][2][4];
#pragma unroll
    for (int mt = 0; mt < 2; mt++)
#pragma unroll
        for (int nt = 0; nt < 2; nt++)
#pragma unroll
            for (int e = 0; e < 4; e++) acc[mt][nt][e] = 0.0f;

    float sa[2][2] = {};
    float sbn[2]   = {};
    const bool awarp = ((wid & 3) == 0);
    const bool bwarp = ((wid >> 2) == 0);

    for (int c = 0; c < NCH; c++) {
        if (c < NCH - 1) asm volatile("cp.async.wait_group 1;" ::: "memory");
        else             asm volatile("cp.async.wait_group 0;" ::: "memory");
        __syncthreads();

        const float* As = (const float*)(dyn + (c & 1) * BUFB);
        const float* Bs = (const float*)(dyn + (c & 1) * BUFB + MATB);

#pragma unroll
        for (int s = 0; s < KC / 8; s++) {
            float a[2][4];
#pragma unroll
            for (int mt = 0; mt < 2; mt++) {
                const float* p = As + (wm + mt * 16 + g) * PITCH + s * 8 + tg;
                a[mt][0] = p[0];
                a[mt][2] = p[4];
                a[mt][1] = p[8 * PITCH];
                a[mt][3] = p[8 * PITCH + 4];
            }
            float b[2][2];
#pragma unroll
            for (int nt = 0; nt < 2; nt++) {
                const float* p = Bs + (wn + nt * 8 + g) * PITCH + s * 8 + tg;
                b[nt][0] = p[0];
                b[nt][1] = p[4];
            }
            if (awarp) {
#pragma unroll
                for (int mt = 0; mt < 2; mt++) {
                    sa[mt][0] += a[mt][0] * a[mt][0] + a[mt][2] * a[mt][2];
                    sa[mt][1] += a[mt][1] * a[mt][1] + a[mt][3] * a[mt][3];
                }
            }
            if (bwarp) {
#pragma unroll
                for (int nt = 0; nt < 2; nt++)
                    sbn[nt] += b[nt][0] * b[nt][0] + b[nt][1] * b[nt][1];
            }
#pragma unroll
            for (int mt = 0; mt < 2; mt++)
#pragma unroll
                for (int nt = 0; nt < 2; nt++)
                    mma_tf32(acc[mt][nt][0], acc[mt][nt][1], acc[mt][nt][2], acc[mt][nt][3],
                             a[mt][0], a[mt][1], a[mt][2], a[mt][3],
                             b[nt][0], b[nt][1]);
        }
        __syncthreads();
        if (c + 2 < NCH) issue(c + 2, c & 1);
    }

    // fused-norm reduce
    if (awarp) {
#pragma unroll
        for (int mt = 0; mt < 2; mt++)
#pragma unroll
            for (int h = 0; h < 2; h++) {
                float v = sa[mt][h];
                v += __shfl_xor_sync(0xffffffffu, v, 1);
                v += __shfl_xor_sync(0xffffffffu, v, 2);
                if (tg == 0) sqA_s[wm + mt * 16 + h * 8 + g] = v;
            }
    }
    if (bwarp) {
#pragma unroll
        for (int nt = 0; nt < 2; nt++) {
            float v = sbn[nt];
            v += __shfl_xor_sync(0xffffffffu, v, 1);
            v += __shfl_xor_sync(0xffffffffu, v, 2);
            if (tg == 0) sqB_s[wn + nt * 8 + g] = v;
        }
    }
    __syncthreads();

    // epilogue: d = sqrt(relu(sqA + sqB - 2 dot)); store + mirror
    const bool offdiag = (bi != bj);
#pragma unroll
    for (int mt = 0; mt < 2; mt++) {
        const int r0 = wm + mt * 16 + g;
        const float sq0 = sqA_s[r0];
        const float sq1 = sqA_s[r0 + 8];
        const int gi0 = bm + r0, gi1 = gi0 + 8;
#pragma unroll
        for (int nt = 0; nt < 2; nt++) {
            const int cc = wn + nt * 8 + 2 * tg;
            const float sb0 = sqB_s[cc], sb1 = sqB_s[cc + 1];
            const int gj0 = bn + cc, gj1 = gj0 + 1;
            float2 o0, o1;
            o0.x = sqrtf(fmaxf(sq0 + sb0 - 2.0f * acc[mt][nt][0], 0.0f));
            o0.y = sqrtf(fmaxf(sq0 + sb1 - 2.0f * acc[mt][nt][1], 0.0f));
            o1.x = sqrtf(fmaxf(sq1 + sb0 - 2.0f * acc[mt][nt][2], 0.0f));
            o1.y = sqrtf(fmaxf(sq1 + sb1 - 2.0f * acc[mt][nt][3], 0.0f));
            *(float2*)(D + (size_t)gi0 * NN + gj0) = o0;
            *(float2*)(D + (size_t)gi1 * NN + gj0) = o1;
            if (offdiag) {
                D[(size_t)gj0 * NN + gi0] = o0.x;
                D[(size_t)gj1 * NN + gi0] = o0.y;
                D[(size_t)gj0 * NN + gi1] = o1.x;
                D[(size_t)gj1 * NN + gi1] = o1.y;
            }
        }
    }
}

// ---------------------------------------------------------------------------
// Kernel 2: per-anchor loss, label-free main loop (R8-proven), with early
// LDG prefetch so global latencies overlap the sort. Fused final reduce.
//   loss_i = sum_{all j} f(d_ij) - sum_{j in pos(i)} f(d_ij)
//   f(t) = SS[idx] - (npos - idx) * t,  idx = #{p : dp <= t},  t = d - margin
// ---------------------------------------------------------------------------
__global__ __launch_bounds__(256) void anchor_loss_kernel(
    const float* __restrict__ D, const int* __restrict__ labels, int N,
    float* __restrict__ out)
{
    __shared__ float posv[128];
    __shared__ float sorted[128];
    __shared__ float ss[129];
    __shared__ float red[8];
    __shared__ int   sh_islast;

    const int i = blockIdx.x;
    const int tid = threadIdx.x;
    const int lane = tid & 31;
    const int wid = tid >> 5;
    const int li = __ldg(&labels[i]);
    const float* row = D + (size_t)i * N;
    const int npos = g_clscnt[li];

    // early prefetch: main-loop row values (used after the sort barrier)
    float t0 = __ldg(&row[tid]);
    float t1 = __ldg(&row[tid + 256]);
    float t2 = __ldg(&row[tid + 512]);
    float t3 = __ldg(&row[tid + 768]);

    if (tid < 128) sorted[tid] = 3.0e30f;                 // INF pad
    if (tid < npos) posv[tid] = __ldg(&row[g_clsidx[li * 128 + tid]]);
    __syncthreads();

    // stable rank sort (npos <= 128)
    if (tid < npos) {
        float v = posv[tid];
        int rank = 0;
        for (int j = 0; j < npos; j++) {
            float w = posv[j];
            rank += (w < v) || (w == v && j < tid);
        }
        sorted[rank] = v;
    }
    __syncthreads();

    // warp 0: suffix sums over 128 slots
    if (tid < 32) {
        float v0 = (4 * tid + 0 < npos) ? sorted[4 * tid + 0] : 0.f;
        float v1 = (4 * tid + 1 < npos) ? sorted[4 * tid + 1] : 0.f;
        float v2 = (4 * tid + 2 < npos) ? sorted[4 * tid + 2] : 0.f;
        float v3 = (4 * tid + 3 < npos) ? sorted[4 * tid + 3] : 0.f;
        float s3 = v3, s2 = v2 + s3, s1 = v1 + s2, s0 = v0 + s1;
        float x = s0;
#pragma unroll
        for (int d = 1; d < 32; d <<= 1) {
            float y = __shfl_down_sync(0xffffffffu, x, d);
            if (tid + d < 32) x += y;
        }
        float carry = x - s0;
        ss[4 * tid + 0] = s0 + carry;
        ss[4 * tid + 1] = s1 + carry;
        ss[4 * tid + 2] = s2 + carry;
        ss[4 * tid + 3] = s3 + carry;
        if (tid == 0) ss[128] = 0.f;
    }
    __syncthreads();

    const float fnp = (float)npos;
    float tv[4] = { t0 - MARGIN, t1 - MARGIN, t2 - MARGIN, t3 - MARGIN };
    float sum = 0.0f;
#pragma unroll
    for (int q = 0; q < 4; q++) {
        float t = tv[q];
        int pos = 0;
#pragma unroll
        for (int s = 64; s > 0; s >>= 1)
            if (sorted[pos + s - 1] <= t) pos += s;
        sum += ss[pos] - (fnp - (float)pos) * t;
    }
    // subtract positive-j contributions (float-identical search)
    if (tid < npos) {
        float t = sorted[tid] - MARGIN;
        int pos = 0;
#pragma unroll
        for (int s = 64; s > 0; s >>= 1)
            if (sorted[pos + s - 1] <= t) pos += s;
        sum -= ss[pos] - (fnp - (float)pos) * t;
    }

    // shfl warp reduce -> 8 partials -> thread 0 (deterministic)
#pragma unroll
    for (int o = 16; o; o >>= 1) sum += __shfl_xor_sync(0xffffffffu, sum, o);
    if (lane == 0) red[wid] = sum;
    __syncthreads();
    if (tid == 0) {
        float tot = 0.f;
#pragma unroll
        for (int w = 0; w < 8; w++) tot += red[w];
        g_losses[i] = tot;
        __threadfence();
        unsigned v = atomicAdd(&g_count, 1u);
        sh_islast = (v == (unsigned)(gridDim.x - 1));
    }
    __syncthreads();

    if (sh_islast) {
        float s = 0.0f;
        for (int j = tid; j < N; j += 256) s += g_losses[j];
#pragma unroll
        for (int o = 16; o; o >>= 1) s += __shfl_xor_sync(0xffffffffu, s, o);
        if (lane == 0) red[wid] = s;
        __syncthreads();
        if (tid == 0) {
            float tot = 0.f;
#pragma unroll
            for (int w = 0; w < 8; w++) tot += red[w];
            out[0] = tot / ((float)N + 1e-8f);
            g_count = 0u;
        }
    }
}

// ---------------------------------------------------------------------------
extern "C" void kernel_launch(void* const* d_in, const int* in_sizes, int n_in,
                              void* d_out, int out_size)
{
    const float* features = (const float*)d_in[0];
    const int*   labels   = (const int*)d_in[1];
    float*       out      = (float*)d_out;

    const int N = in_sizes[1];            // 1024

    float* D;
    cudaGetSymbolAddress((void**)&D, g_dist);

    cudaFuncSetAttribute(dist_mma_kernel,
                         cudaFuncAttributeMaxDynamicSharedMemorySize, DYNB);

    const int nb = NN / TILE;             // 16 -> 136 CTAs
    dist_mma_kernel<<<nb * (nb + 1) / 2, 256, DYNB>>>(features, labels, D);
    anchor_loss_kernel<<<N, 256>>>(D, labels, N, out);
}

// round 13
// speedup vs baseline: 1.2670x; 1.0904x over previous
#include <cuda_runtime.h>
#include <cstdint>
#include <math.h>

#define NN 1024
#define KK 512
#define TILE 64            // CTA tile (square, triangular-symmetric)
#define KC 64              // k-chunk
#define NCH (KK / KC)      // 8
#define MARGIN 1.0f

#define PITCH 68           // floats per smem row (pad 4 -> conflict-free frags)
#define PITCHB (PITCH * 4) // 272 B
#define MATB (TILE * PITCHB)   // 17408 per matrix
#define BUFB (2 * MATB)        // 34816 per buffer (A+B)
#define DYNB (2 * BUFB)        // 69632 double-buffered

// Scratch (device globals — allocation forbidden)
__device__ float g_dist[NN * NN];
__device__ float g_losses[NN];
__device__ unsigned int g_count;   // zero-init; self-resets each launch

// ---------------------------------------------------------------------------
static __device__ __forceinline__ uint32_t sptr(const void* p) {
    uint32_t a;
    asm("{ .reg .u64 t; cvta.to.shared.u64 t, %1; cvt.u32.u64 %0, t; }"
        : "=r"(a) : "l"(p));
    return a;
}
static __device__ __forceinline__ void cp16(uint32_t dst, const void* src) {
    asm volatile("cp.async.cg.shared.global [%0], [%1], 16;" :: "r"(dst), "l"(src));
}
#define CP_COMMIT() asm volatile("cp.async.commit_group;" ::: "memory")

static __device__ __forceinline__ void mma_tf32(
    float& d0, float& d1, float& d2, float& d3,
    float a0, float a1, float a2, float a3, float b0, float b1)
{
    asm volatile(
        "mma.sync.aligned.m16n8k8.row.col.f32.tf32.tf32.f32 "
        "{%0,%1,%2,%3}, {%4,%5,%6,%7}, {%8,%9}, {%0,%1,%2,%3};"
        : "+f"(d0), "+f"(d1), "+f"(d2), "+f"(d3)
        : "r"(__float_as_uint(a0)), "r"(__float_as_uint(a1)),
          "r"(__float_as_uint(a2)), "r"(__float_as_uint(a3)),
          "r"(__float_as_uint(b0)), "r"(__float_as_uint(b1)));
}

// ---------------------------------------------------------------------------
// Kernel 1: tf32 mma.sync symmetric distance GEMM (byte-identical to R7).
// 136 CTAs (triangular 64x64 tiles), 256 thr, 2-stage cp.async.
// ---------------------------------------------------------------------------
__global__ __launch_bounds__(256) void dist_mma_kernel(
    const float* __restrict__ X, float* __restrict__ D)
{
    extern __shared__ __align__(16) char dyn[];
    __shared__ float sqA_s[TILE], sqB_s[TILE];

    const int tid  = threadIdx.x;
    const int wid  = tid >> 5;
    const int lane = tid & 31;
    const int g    = lane >> 2;
    const int tg   = lane & 3;

    const int nb = NN / TILE;          // 16
    int rem = blockIdx.x, bi = 0;
    while (rem >= nb - bi) { rem -= nb - bi; bi++; }
    const int bj = bi + rem;
    const int bm = bi * TILE;
    const int bn = bj * TILE;

    const int wm = (wid >> 2) * 32;
    const int wn = (wid & 3) * 16;

    const uint32_t smem = sptr(dyn);

    auto issue = [&](int c, int buf) {
        const uint32_t sb = smem + buf * BUFB;
        const float* XA = X + (size_t)bm * KK + c * KC;
        const float* XB = X + (size_t)bn * KK + c * KC;
#pragma unroll
        for (int it = 0; it < 4; it++) {
            int idx = tid + it * 256;
            int row = idx >> 4;
            int kq  = idx & 15;
            uint32_t doff = row * PITCHB + kq * 16;
            cp16(sb + doff,        XA + (size_t)row * KK + kq * 4);
            cp16(sb + MATB + doff, XB + (size_t)row * KK + kq * 4);
        }
        CP_COMMIT();
    };

    issue(0, 0);
    issue(1, 1);

    float acc[2][2][4];
#pragma unroll
    for (int mt = 0; mt < 2; mt++)
#pragma unroll
        for (int nt = 0; nt < 2; nt++)
#pragma unroll
            for (int e = 0; e < 4; e++) acc[mt][nt][e] = 0.0f;

    float sa[2][2] = {};
    float sbn[2]   = {};
    const bool awarp = ((wid & 3) == 0);
    const bool bwarp = ((wid >> 2) == 0);

    for (int c = 0; c < NCH; c++) {
        if (c < NCH - 1) asm volatile("cp.async.wait_group 1;" ::: "memory");
        else             asm volatile("cp.async.wait_group 0;" ::: "memory");
        __syncthreads();

        const float* As = (const float*)(dyn + (c & 1) * BUFB);
        const float* Bs = (const float*)(dyn + (c & 1) * BUFB + MATB);

#pragma unroll
        for (int s = 0; s < KC / 8; s++) {
            float a[2][4];
#pragma unroll
            for (int mt = 0; mt < 2; mt++) {
                const float* p = As + (wm + mt * 16 + g) * PITCH + s * 8 + tg;
                a[mt][0] = p[0];
                a[mt][2] = p[4];
                a[mt][1] = p[8 * PITCH];
                a[mt][3] = p[8 * PITCH + 4];
            }
            float b[2][2];
#pragma unroll
            for (int nt = 0; nt < 2; nt++) {
                const float* p = Bs + (wn + nt * 8 + g) * PITCH + s * 8 + tg;
                b[nt][0] = p[0];
                b[nt][1] = p[4];
            }
            if (awarp) {
#pragma unroll
                for (int mt = 0; mt < 2; mt++) {
                    sa[mt][0] += a[mt][0] * a[mt][0] + a[mt][2] * a[mt][2];
                    sa[mt][1] += a[mt][1] * a[mt][1] + a[mt][3] * a[mt][3];
                }
            }
            if (bwarp) {
#pragma unroll
                for (int nt = 0; nt < 2; nt++)
                    sbn[nt] += b[nt][0] * b[nt][0] + b[nt][1] * b[nt][1];
            }
#pragma unroll
            for (int mt = 0; mt < 2; mt++)
#pragma unroll
                for (int nt = 0; nt < 2; nt++)
                    mma_tf32(acc[mt][nt][0], acc[mt][nt][1], acc[mt][nt][2], acc[mt][nt][3],
                             a[mt][0], a[mt][1], a[mt][2], a[mt][3],
                             b[nt][0], b[nt][1]);
        }
        __syncthreads();
        if (c + 2 < NCH) issue(c + 2, c & 1);
    }

    // fused-norm reduce
    if (awarp) {
#pragma unroll
        for (int mt = 0; mt < 2; mt++)
#pragma unroll
            for (int h = 0; h < 2; h++) {
                float v = sa[mt][h];
                v += __shfl_xor_sync(0xffffffffu, v, 1);
                v += __shfl_xor_sync(0xffffffffu, v, 2);
                if (tg == 0) sqA_s[wm + mt * 16 + h * 8 + g] = v;
            }
    }
    if (bwarp) {
#pragma unroll
        for (int nt = 0; nt < 2; nt++) {
            float v = sbn[nt];
            v += __shfl_xor_sync(0xffffffffu, v, 1);
            v += __shfl_xor_sync(0xffffffffu, v, 2);
            if (tg == 0) sqB_s[wn + nt * 8 + g] = v;
        }
    }
    __syncthreads();

    // epilogue: d = sqrt(relu(sqA + sqB - 2 dot)); store + mirror
    const bool offdiag = (bi != bj);
#pragma unroll
    for (int mt = 0; mt < 2; mt++) {
        const int r0 = wm + mt * 16 + g;
        const float sq0 = sqA_s[r0];
        const float sq1 = sqA_s[r0 + 8];
        const int gi0 = bm + r0, gi1 = gi0 + 8;
#pragma unroll
        for (int nt = 0; nt < 2; nt++) {
            const int cc = wn + nt * 8 + 2 * tg;
            const float sb0 = sqB_s[cc], sb1 = sqB_s[cc + 1];
            const int gj0 = bn + cc, gj1 = gj0 + 1;
            float2 o0, o1;
            o0.x = sqrtf(fmaxf(sq0 + sb0 - 2.0f * acc[mt][nt][0], 0.0f));
            o0.y = sqrtf(fmaxf(sq0 + sb1 - 2.0f * acc[mt][nt][1], 0.0f));
            o1.x = sqrtf(fmaxf(sq1 + sb0 - 2.0f * acc[mt][nt][2], 0.0f));
            o1.y = sqrtf(fmaxf(sq1 + sb1 - 2.0f * acc[mt][nt][3], 0.0f));
            *(float2*)(D + (size_t)gi0 * NN + gj0) = o0;
            *(float2*)(D + (size_t)gi1 * NN + gj0) = o1;
            if (offdiag) {
                D[(size_t)gj0 * NN + gi0] = o0.x;
                D[(size_t)gj1 * NN + gi0] = o0.y;
                D[(size_t)gj0 * NN + gi1] = o1.x;
                D[(size_t)gj1 * NN + gi1] = o1.y;
            }
        }
    }
}

// ---------------------------------------------------------------------------
// Kernel 2: per-anchor loss with FULLY PARALLEL positive compaction.
// All 8 warps ballot their chunks concurrently; warp 0 does one shfl prefix
// over the 32 chunk counts; positives scattered from registers.
// Then sorted-positives + suffix-sums + branchless binary search (R9-proven).
// Fused last-block final reduce.
// ---------------------------------------------------------------------------
__global__ __launch_bounds__(256) void anchor_loss_kernel(
    const float* __restrict__ D, const int* __restrict__ labels,
    float* __restrict__ out)
{
    __shared__ unsigned balS[32];
    __shared__ int      pref[32];
    __shared__ int      sh_npos;
    __shared__ float    posv[128];
    __shared__ float    sorted[128];
    __shared__ float    ss[132];
    __shared__ float    red[8];
    __shared__ int      sh_islast;

    const int i = blockIdx.x;
    const int tid = threadIdx.x;
    const int lane = tid & 31;
    const int wid = tid >> 5;
    const int li = __ldg(&labels[i]);
    const float* row = D + (size_t)i * NN;

    // parallel load: 4 distances + 4 labels per thread (coalesced)
    float tv[4];
    int   lb[4];
#pragma unroll
    for (int q = 0; q < 4; q++) {
        tv[q] = __ldg(&row[tid + q * 256]);
        lb[q] = __ldg(&labels[tid + q * 256]);
    }
    if (tid < 128) sorted[tid] = 3.0e30f;     // INF pad

    // parallel ballots: chunk (wid + q*8) covers j = tid + q*256
    unsigned bq[4];
#pragma unroll
    for (int q = 0; q < 4; q++) {
        bq[q] = __ballot_sync(0xffffffffu, lb[q] == li);
        if (lane == 0) balS[wid + q * 8] = bq[q];
    }
    __syncthreads();

    // warp 0: exclusive prefix over the 32 chunk popcounts
    if (tid < 32) {
        int c = __popc(balS[tid]);
        int x = c;
#pragma unroll
        for (int d = 1; d < 32; d <<= 1) {
            int y = __shfl_up_sync(0xffffffffu, x, d);
            if (lane >= d) x += y;
        }
        pref[tid] = x - c;                    // exclusive prefix
        if (tid == 31) sh_npos = x;           // total
    }
    __syncthreads();

    const int npos = sh_npos < 128 ? sh_npos : 128;

    // scatter positives from registers (deterministic order)
#pragma unroll
    for (int q = 0; q < 4; q++) {
        if (lb[q] == li) {
            int p = pref[wid + q * 8] + __popc(bq[q] & ((1u << lane) - 1u));
            if (p < 128) posv[p] = tv[q];
        }
    }
    __syncthreads();

    // stable rank sort (npos <= 128)
    if (tid < npos) {
        float v = posv[tid];
        int rank = 0;
        for (int j = 0; j < npos; j++) {
            float w = posv[j];
            rank += (w < v) || (w == v && j < tid);
        }
        sorted[rank] = v;
    }
    __syncthreads();

    // warp 0: suffix sums over 128 slots
    if (tid < 32) {
        float v0 = (4 * tid + 0 < npos) ? sorted[4 * tid + 0] : 0.f;
        float v1 = (4 * tid + 1 < npos) ? sorted[4 * tid + 1] : 0.f;
        float v2 = (4 * tid + 2 < npos) ? sorted[4 * tid + 2] : 0.f;
        float v3 = (4 * tid + 3 < npos) ? sorted[4 * tid + 3] : 0.f;
        float s3 = v3, s2 = v2 + s3, s1 = v1 + s2, s0 = v0 + s1;
        float x = s0;
#pragma unroll
        for (int d = 1; d < 32; d <<= 1) {
            float y = __shfl_down_sync(0xffffffffu, x, d);
            if (tid + d < 32) x += y;
        }
        float carry = x - s0;
        ss[4 * tid + 0] = s0 + carry;
        ss[4 * tid + 1] = s1 + carry;
        ss[4 * tid + 2] = s2 + carry;
        ss[4 * tid + 3] = s3 + carry;
        if (tid == 0) ss[128] = 0.f;
    }
    __syncthreads();

    // main loop over ALL j (label-free): branchless 7-step binary search
    const float fnp = (float)npos;
    float sum = 0.0f;
#pragma unroll
    for (int q = 0; q < 4; q++) {
        float t = tv[q] - MARGIN;
        int pos = 0;
#pragma unroll
        for (int s = 64; s > 0; s >>= 1)
            if (sorted[pos + s - 1] <= t) pos += s;
        sum += ss[pos] - (fnp - (float)pos) * t;
    }
    // subtract positive-j contributions (float-identical search)
    if (tid < npos) {
        float t = sorted[tid] - MARGIN;
        int pos = 0;
#pragma unroll
        for (int s = 64; s > 0; s >>= 1)
            if (sorted[pos + s - 1] <= t) pos += s;
        sum -= ss[pos] - (fnp - (float)pos) * t;
    }

    // shfl warp reduce -> 8 partials -> thread 0 (deterministic)
#pragma unroll
    for (int o = 16; o; o >>= 1) sum += __shfl_xor_sync(0xffffffffu, sum, o);
    if (lane == 0) red[wid] = sum;
    __syncthreads();
    if (tid == 0) {
        float tot = 0.f;
#pragma unroll
        for (int w = 0; w < 8; w++) tot += red[w];
        g_losses[i] = tot;
        __threadfence();
        unsigned v = atomicAdd(&g_count, 1u);
        sh_islast = (v == (unsigned)(gridDim.x - 1));
    }
    __syncthreads();

    // last-done block: deterministic final reduce
    if (sh_islast) {
        float s = 0.0f;
        for (int j = tid; j < NN; j += 256) s += g_losses[j];
#pragma unroll
        for (int o = 16; o; o >>= 1) s += __shfl_xor_sync(0xffffffffu, s, o);
        if (lane == 0) red[wid] = s;
        __syncthreads();
        if (tid == 0) {
            float tot = 0.f;
#pragma unroll
            for (int w = 0; w < 8; w++) tot += red[w];
            out[0] = tot / ((float)NN + 1e-8f);
            g_count = 0u;
        }
    }
}

// ---------------------------------------------------------------------------
extern "C" void kernel_launch(void* const* d_in, const int* in_sizes, int n_in,
                              void* d_out, int out_size)
{
    const float* features = (const float*)d_in[0];
    const int*   labels   = (const int*)d_in[1];
    float*       out      = (float*)d_out;

    float* D;
    cudaGetSymbolAddress((void**)&D, g_dist);

    cudaFuncSetAttribute(dist_mma_kernel,
                         cudaFuncAttributeMaxDynamicSharedMemorySize, DYNB);

    const int nb = NN / TILE;             // 16 -> 136 CTAs
    dist_mma_kernel<<<nb * (nb + 1) / 2, 256, DYNB>>>(features, D);
    anchor_loss_kernel<<<NN, 256>>>(D, labels, out);
}